// round 12
// baseline (speedup 1.0000x reference)
#include <cuda_runtime.h>

// LSTM_46316927320185 — R12: dual-chain lanes (R11) + uniform 148-SM grid (R9) + init fold
// B=4096, T=512, EMB=32, HID=16, VOCAB=50000.
//
// R11 proved 2-elems-per-lane ILP improves per-elem cost ~8% (18.9 vs 20.4
// cyc/elem-step) but its 128-CTA grid idled 20 SMs and net-regressed. R12:
//  - warp = 4 elems (2 per lane, dual independent chains, shared wk regs)
//  - grid 148 x 224thr (7 warps, 28 elems/CTA; 4144 >= 4096, tail clamped).
//    Loop has only __syncwarp -> warps independent; uneven SMSP split harmless.
//  - xp fold: accumulators init to pack2(xp_gate, 0) -> kills 4 FADD/elem-step
//    on the FMA pipe (xp add comes free out of hadd2).
//  - table kernel: embed rows via LDG.128 (same accumulation order).

#define HID    16
#define EMB    32
#define T_LEN  512
#define BATCH  4096
#define VOCAB  50000

typedef unsigned long long u64;

// [v*HID + j] -> float4 (xp_i/2, xp_f/2, xp_g, xp_o/2), biases folded. 12.8 MB.
__device__ float4 g_tbl[(size_t)VOCAB * HID];

__device__ __forceinline__ u64 fma2(u64 a, u64 b, u64 c) {
    u64 d; asm("fma.rn.f32x2 %0, %1, %2, %3;" : "=l"(d) : "l"(a), "l"(b), "l"(c)); return d;
}
__device__ __forceinline__ u64 mul2(u64 a, u64 b) {
    u64 d; asm("mul.rn.f32x2 %0, %1, %2;" : "=l"(d) : "l"(a), "l"(b)); return d;
}
__device__ __forceinline__ u64 rep2(float v) {
    u64 r; asm("mov.b64 %0, {%1, %1};" : "=l"(r) : "f"(v)); return r;
}
__device__ __forceinline__ u64 pack2(float a, float b) {
    u64 r; asm("mov.b64 %0, {%1, %2};" : "=l"(r) : "f"(a), "f"(b)); return r;
}
__device__ __forceinline__ void unpack2(u64 v, float& lo, float& hi) {
    asm("mov.b64 {%0, %1}, %2;" : "=f"(lo), "=f"(hi) : "l"(v));
}
__device__ __forceinline__ float hadd2(u64 v) {
    float lo, hi; unpack2(v, lo, hi); return lo + hi;
}
__device__ __forceinline__ float tanh_ap(float x) {
    float y; asm("tanh.approx.f32 %0, %1;" : "=f"(y) : "f"(x)); return y;
}

// ============ Phase A: per-vocab projection table ============
#define PT_THREADS 256
#define PT_GRID    ((VOCAB * HID) / PT_THREADS)   // 3125

__global__ __launch_bounds__(PT_THREADS)
void proj_table_kernel(const float* __restrict__ embed,
                       const float* __restrict__ w_ih,
                       const float* __restrict__ b_ih,
                       const float* __restrict__ b_hh)
{
    // gate-packed transposed weights: [k*HID+j] = ((wi,wf),(wg,wo))
    __shared__ ulonglong2 w_u[EMB * HID];   // 8 KB

    const int tid = threadIdx.x;
    for (int i = tid; i < EMB * HID; i += PT_THREADS) {
        int k = i / HID, jj = i % HID;
        float4 w = make_float4(w_ih[(0 * HID + jj) * EMB + k],
                               w_ih[(1 * HID + jj) * EMB + k],
                               w_ih[(2 * HID + jj) * EMB + k],
                               w_ih[(3 * HID + jj) * EMB + k]);
        *(float4*)&w_u[i] = w;
    }
    __syncthreads();

    const int gid = blockIdx.x * PT_THREADS + tid;
    const int v = gid >> 4;        // vocab row
    const int j = gid & 15;        // hidden unit

    const float4* er4 = (const float4*)(embed + (size_t)v * EMB);
    u64 a01 = 0ull, a23 = 0ull;
    #pragma unroll
    for (int c4 = 0; c4 < 8; ++c4) {
        const float4 ev = er4[c4];              // LDG.128, broadcast across j-lanes
        u64 q;
        q = rep2(ev.x);
        { const ulonglong2 w = w_u[(c4 * 4 + 0) * HID + j];
          a01 = fma2(q, w.x, a01); a23 = fma2(q, w.y, a23); }
        q = rep2(ev.y);
        { const ulonglong2 w = w_u[(c4 * 4 + 1) * HID + j];
          a01 = fma2(q, w.x, a01); a23 = fma2(q, w.y, a23); }
        q = rep2(ev.z);
        { const ulonglong2 w = w_u[(c4 * 4 + 2) * HID + j];
          a01 = fma2(q, w.x, a01); a23 = fma2(q, w.y, a23); }
        q = rep2(ev.w);
        { const ulonglong2 w = w_u[(c4 * 4 + 3) * HID + j];
          a01 = fma2(q, w.x, a01); a23 = fma2(q, w.y, a23); }
    }
    float ai, af, ag, ao;
    unpack2(a01, ai, af);
    unpack2(a23, ag, ao);
    // gates i,f,o pre-scaled by 0.5 (sigmoid identity); g unscaled (tanh)
    g_tbl[gid] = make_float4(0.5f * (ai + b_ih[j]           + b_hh[j]),
                             0.5f * (af + b_ih[HID + j]     + b_hh[HID + j]),
                                     ag + b_ih[2 * HID + j] + b_hh[2 * HID + j],
                             0.5f * (ao + b_ih[3 * HID + j] + b_hh[3 * HID + j]));
}

// ============ Phase B: recurrence — 4 elems/warp (2/lane), 148-CTA grid ============
#define RC_WARPS   7
#define RC_THREADS 224                 // 7 warps
#define RC_EPW     4                   // elems per warp
#define RC_EPC     28                  // 7 * 4
#define RC_GRID    148                 // 148*28 = 4144 >= 4096 (tail clamped)

__global__ __launch_bounds__(RC_THREADS, 1)
void recur_kernel(const int*   __restrict__ x,
                  const float* __restrict__ w_hh,
                  const float* __restrict__ fc_w,
                  const float* __restrict__ fc_b,
                  float*       __restrict__ out)
{
    // double-buffered h staging: [buf][warp][local elem][j]  (14 KB)
    __shared__ float h_s[2][RC_WARPS][RC_EPW][HID];

    const int tid  = threadIdx.x;
    const int warp = tid >> 5, lane = tid & 31;
    const int eh   = lane >> 4;          // lane group: owns elems {2eh, 2eh+1}
    const int j    = lane & 15;          // hidden unit owned
    const int le0  = eh * 2;             // local elem base within warp
    const int b0   = blockIdx.x * RC_EPC + warp * RC_EPW + le0;
    const int bc0  = (b0 + 0 < BATCH) ? (b0 + 0) : (BATCH - 1);  // read clamps
    const int bc1  = (b0 + 1 < BATCH) ? (b0 + 1) : (BATCH - 1);

    // K-pair packed recurrent weights, SHARED by the lane's 2 elems:
    // wk[g][i] = (w[g,j,2i], w[g,j,2i+1]); gates i,f,o halved (sigmoid fold).
    u64 wk[4][8];
    #pragma unroll
    for (int g = 0; g < 4; ++g) {
        const u64* wr = (const u64*)(w_hh + (size_t)(g * HID + j) * HID);
        #pragma unroll
        for (int i = 0; i < 8; ++i) wk[g][i] = wr[i];
    }
    {
        const u64 hlf = rep2(0.5f);
        #pragma unroll
        for (int i = 0; i < 8; ++i) {
            wk[0][i] = mul2(wk[0][i], hlf);
            wk[1][i] = mul2(wk[1][i], hlf);
            wk[3][i] = mul2(wk[3][i], hlf);
        }
    }

    const int* xcol0 = x + (size_t)bc0 * T_LEN;
    const int* xcol1 = x + (size_t)bc1 * T_LEN;

    // gather pipeline per elem: rows for t (xc), t+1 (xn); index for t+2 (i2)
    float4 xc[2], xn[2];
    int    i2[2];
    xc[0] = g_tbl[(size_t)xcol0[0] * HID + j];
    xc[1] = g_tbl[(size_t)xcol1[0] * HID + j];
    xn[0] = g_tbl[(size_t)xcol0[1] * HID + j];
    xn[1] = g_tbl[(size_t)xcol1[1] * HID + j];
    i2[0] = xcol0[2];
    i2[1] = xcol1[2];

    float h[2] = {0.f, 0.f}, c[2] = {0.f, 0.f};

    #pragma unroll 2
    for (int t = 0; t < T_LEN; ++t) {
        const int buf = t & 1;
        h_s[buf][warp][le0 + 0][j] = h[0];
        h_s[buf][warp][le0 + 1][j] = h[1];
        __syncwarp();

        // kick next gathers early (t+2 rows; t+3 indices) — overlap with matvec
        const int tn = (t + 3 < T_LEN) ? (t + 3) : (T_LEN - 1);
        const float4 x2_0 = g_tbl[(size_t)i2[0] * HID + j];
        const float4 x2_1 = g_tbl[(size_t)i2[1] * HID + j];
        const int    i3_0 = xcol0[tn];
        const int    i3_1 = xcol1[tn];

        // two independent chains (elem 0 / elem 1) — compiler interleaves
        #pragma unroll
        for (int e = 0; e < 2; ++e) {
            const ulonglong2* hp = (const ulonglong2*)h_s[buf][warp][le0 + e];
            // xp folded into accumulator init (saves 4 FADD on the fma pipe)
            u64 a0 = pack2(xc[e].x, 0.f);
            u64 a1 = pack2(xc[e].y, 0.f);
            u64 a2 = pack2(xc[e].z, 0.f);
            u64 a3 = pack2(xc[e].w, 0.f);
            #pragma unroll
            for (int i = 0; i < 4; ++i) {
                const ulonglong2 hv = hp[i];
                a0 = fma2(hv.x, wk[0][2 * i], a0); a0 = fma2(hv.y, wk[0][2 * i + 1], a0);
                a1 = fma2(hv.x, wk[1][2 * i], a1); a1 = fma2(hv.y, wk[1][2 * i + 1], a1);
                a2 = fma2(hv.x, wk[2][2 * i], a2); a2 = fma2(hv.y, wk[2][2 * i + 1], a2);
                a3 = fma2(hv.x, wk[3][2 * i], a3); a3 = fma2(hv.y, wk[3][2 * i + 1], a3);
            }
            const float si = hadd2(a0);   // xp included; i,f,o pre-scaled by 0.5
            const float sf = hadd2(a1);
            const float sg = hadd2(a2);   // unscaled (tanh gate)
            const float so = hadd2(a3);

            const float ig = fmaf(tanh_ap(si), 0.5f, 0.5f);
            const float fg = fmaf(tanh_ap(sf), 0.5f, 0.5f);
            const float gg = tanh_ap(sg);
            const float og = fmaf(tanh_ap(so), 0.5f, 0.5f);
            c[e] = fg * c[e] + ig * gg;
            h[e] = og * tanh_ap(c[e]);
        }

        xc[0] = xn[0]; xn[0] = x2_0; i2[0] = i3_0;
        xc[1] = xn[1]; xn[1] = x2_1; i2[1] = i3_1;
    }

    // FC head: reduce over j within this 16-lane group (xor 8..1 stays in-group)
    const float fcw = fc_w[j];
    const float fcb = fc_b[0];
    #pragma unroll
    for (int e = 0; e < 2; ++e) {
        float v = h[e] * fcw;
        v += __shfl_xor_sync(0xffffffffu, v, 8);
        v += __shfl_xor_sync(0xffffffffu, v, 4);
        v += __shfl_xor_sync(0xffffffffu, v, 2);
        v += __shfl_xor_sync(0xffffffffu, v, 1);
        if (j == 0 && b0 + e < BATCH)
            out[b0 + e] = fmaf(tanh_ap(0.5f * (v + fcb)), 0.5f, 0.5f);
    }
}

extern "C" void kernel_launch(void* const* d_in, const int* in_sizes, int n_in,
                              void* d_out, int out_size)
{
    const int*   x     = (const int*)  d_in[0];
    const float* embed = (const float*)d_in[1];
    const float* w_ih  = (const float*)d_in[2];
    const float* w_hh  = (const float*)d_in[3];
    const float* b_ih  = (const float*)d_in[4];
    const float* b_hh  = (const float*)d_in[5];
    const float* fc_w  = (const float*)d_in[6];
    const float* fc_b  = (const float*)d_in[7];
    float* out = (float*)d_out;

    proj_table_kernel<<<PT_GRID, PT_THREADS>>>(embed, w_ih, b_ih, b_hh);
    recur_kernel<<<RC_GRID, RC_THREADS>>>(x, w_hh, fc_w, fc_b, out);
}

// round 14
// speedup vs baseline: 1.1240x; 1.1240x over previous
#include <cuda_runtime.h>

// LSTM_46316927320185 — R13 resubmit (prior run lost to infra failure)
// B=4096, T=512, EMB=32, HID=16, VOCAB=50000.
//
// Lessons R9-R12: (1) per-elem instr cost is king (dual-chain 18.9 cyc/elem);
// (2) all 148 SMs must be covered; (3) every SMSP needs >=2 warps (R12's lone
// warp on SMSP3 set the makespan: issue fell 47->38%).
// R13 satisfies all three: grid 148 x 256thr (8 warps = 2/SMSP even);
// 28 elems/CTA distributed warps0-3:4, warps4-7:3 -> exactly 7 elems on every
// SMSP. Inner body is R11's verbatim (plain xc adds; no init-fold).
// Invalid tail elems compute into a private dummy smem slot and mask stores.

#define HID    16
#define EMB    32
#define T_LEN  512
#define BATCH  4096
#define VOCAB  50000

typedef unsigned long long u64;

// [v*HID + j] -> float4 (xp_i/2, xp_f/2, xp_g, xp_o/2), biases folded. 12.8 MB.
__device__ float4 g_tbl[(size_t)VOCAB * HID];

__device__ __forceinline__ u64 fma2(u64 a, u64 b, u64 c) {
    u64 d; asm("fma.rn.f32x2 %0, %1, %2, %3;" : "=l"(d) : "l"(a), "l"(b), "l"(c)); return d;
}
__device__ __forceinline__ u64 mul2(u64 a, u64 b) {
    u64 d; asm("mul.rn.f32x2 %0, %1, %2;" : "=l"(d) : "l"(a), "l"(b)); return d;
}
__device__ __forceinline__ u64 rep2(float v) {
    u64 r; asm("mov.b64 %0, {%1, %1};" : "=l"(r) : "f"(v)); return r;
}
__device__ __forceinline__ void unpack2(u64 v, float& lo, float& hi) {
    asm("mov.b64 {%0, %1}, %2;" : "=f"(lo), "=f"(hi) : "l"(v));
}
__device__ __forceinline__ float hadd2(u64 v) {
    float lo, hi; unpack2(v, lo, hi); return lo + hi;
}
__device__ __forceinline__ float tanh_ap(float x) {
    float y; asm("tanh.approx.f32 %0, %1;" : "=f"(y) : "f"(x)); return y;
}

// ============ Phase A: per-vocab projection table ============
#define PT_THREADS 256
#define PT_GRID    ((VOCAB * HID) / PT_THREADS)   // 3125

__global__ __launch_bounds__(PT_THREADS)
void proj_table_kernel(const float* __restrict__ embed,
                       const float* __restrict__ w_ih,
                       const float* __restrict__ b_ih,
                       const float* __restrict__ b_hh)
{
    // gate-packed transposed weights: [k*HID+j] = ((wi,wf),(wg,wo))
    __shared__ ulonglong2 w_u[EMB * HID];   // 8 KB

    const int tid = threadIdx.x;
    for (int i = tid; i < EMB * HID; i += PT_THREADS) {
        int k = i / HID, jj = i % HID;
        float4 w = make_float4(w_ih[(0 * HID + jj) * EMB + k],
                               w_ih[(1 * HID + jj) * EMB + k],
                               w_ih[(2 * HID + jj) * EMB + k],
                               w_ih[(3 * HID + jj) * EMB + k]);
        *(float4*)&w_u[i] = w;
    }
    __syncthreads();

    const int gid = blockIdx.x * PT_THREADS + tid;
    const int v = gid >> 4;        // vocab row
    const int j = gid & 15;        // hidden unit

    const float4* er4 = (const float4*)(embed + (size_t)v * EMB);
    u64 a01 = 0ull, a23 = 0ull;
    #pragma unroll
    for (int c4 = 0; c4 < 8; ++c4) {
        const float4 ev = er4[c4];              // LDG.128, broadcast across j-lanes
        u64 q;
        q = rep2(ev.x);
        { const ulonglong2 w = w_u[(c4 * 4 + 0) * HID + j];
          a01 = fma2(q, w.x, a01); a23 = fma2(q, w.y, a23); }
        q = rep2(ev.y);
        { const ulonglong2 w = w_u[(c4 * 4 + 1) * HID + j];
          a01 = fma2(q, w.x, a01); a23 = fma2(q, w.y, a23); }
        q = rep2(ev.z);
        { const ulonglong2 w = w_u[(c4 * 4 + 2) * HID + j];
          a01 = fma2(q, w.x, a01); a23 = fma2(q, w.y, a23); }
        q = rep2(ev.w);
        { const ulonglong2 w = w_u[(c4 * 4 + 3) * HID + j];
          a01 = fma2(q, w.x, a01); a23 = fma2(q, w.y, a23); }
    }
    float ai, af, ag, ao;
    unpack2(a01, ai, af);
    unpack2(a23, ag, ao);
    // gates i,f,o pre-scaled by 0.5 (sigmoid identity); g unscaled (tanh)
    g_tbl[gid] = make_float4(0.5f * (ai + b_ih[j]           + b_hh[j]),
                             0.5f * (af + b_ih[HID + j]     + b_hh[HID + j]),
                                     ag + b_ih[2 * HID + j] + b_hh[2 * HID + j],
                             0.5f * (ao + b_ih[3 * HID + j] + b_hh[3 * HID + j]));
}

// ============ Phase B: recurrence — 8 warps, 4/4/4/4/3/3/3/3 elems ============
#define RC_THREADS 256                 // 8 warps -> 2 per SMSP (even)
#define RC_EPC     28                  // elems per CTA
#define RC_GRID    148                 // 148*28 = 4144 >= 4096 (tail masked)
#define RC_SLOTS   36                  // 28 real + 8 per-warp dummy slots

__global__ __launch_bounds__(RC_THREADS, 1)
void recur_kernel(const int*   __restrict__ x,
                  const float* __restrict__ w_hh,
                  const float* __restrict__ fc_w,
                  const float* __restrict__ fc_b,
                  float*       __restrict__ out)
{
    // double-buffered h staging: [buf][local elem slot][j]  (4.5 KB)
    __shared__ float h_s[2][RC_SLOTS][HID];

    const int tid  = threadIdx.x;
    const int warp = tid >> 5, lane = tid & 31;
    const int eh   = lane >> 4;          // lane group
    const int j    = lane & 15;          // hidden unit owned

    // warps 0-3 own 4 elems, warps 4-7 own 3 -> 7 elems on every SMSP
    const int base = (warp < 4) ? (warp * 4) : (16 + (warp - 4) * 3);
    const int le0  = base + eh * 2;                  // first owned local elem
    const bool v1  = (warp < 4) || (eh == 0);        // second elem valid?
    const int le1  = v1 ? (le0 + 1) : (28 + warp);   // dummy slot if invalid

    const int b0  = blockIdx.x * RC_EPC + le0;
    const int b1  = blockIdx.x * RC_EPC + le0 + 1;
    const int bc0 = (b0 < BATCH) ? b0 : (BATCH - 1);             // read clamps
    const int bc1 = (v1 && b1 < BATCH) ? b1 : (BATCH - 1);

    // K-pair packed recurrent weights, SHARED by the lane's 2 chains:
    // wk[g][i] = (w[g,j,2i], w[g,j,2i+1]); gates i,f,o halved (sigmoid fold).
    u64 wk[4][8];
    #pragma unroll
    for (int g = 0; g < 4; ++g) {
        const u64* wr = (const u64*)(w_hh + (size_t)(g * HID + j) * HID);
        #pragma unroll
        for (int i = 0; i < 8; ++i) wk[g][i] = wr[i];
    }
    {
        const u64 hlf = rep2(0.5f);
        #pragma unroll
        for (int i = 0; i < 8; ++i) {
            wk[0][i] = mul2(wk[0][i], hlf);
            wk[1][i] = mul2(wk[1][i], hlf);
            wk[3][i] = mul2(wk[3][i], hlf);
        }
    }

    const int* xcol0 = x + (size_t)bc0 * T_LEN;
    const int* xcol1 = x + (size_t)bc1 * T_LEN;

    // gather pipeline per elem: rows for t (xc), t+1 (xn); index for t+2 (i2)
    float4 xc[2], xn[2];
    int    i2[2];
    xc[0] = g_tbl[(size_t)xcol0[0] * HID + j];
    xc[1] = g_tbl[(size_t)xcol1[0] * HID + j];
    xn[0] = g_tbl[(size_t)xcol0[1] * HID + j];
    xn[1] = g_tbl[(size_t)xcol1[1] * HID + j];
    i2[0] = xcol0[2];
    i2[1] = xcol1[2];

    float h[2] = {0.f, 0.f}, c[2] = {0.f, 0.f};

    #pragma unroll 2
    for (int t = 0; t < T_LEN; ++t) {
        const int buf = t & 1;
        h_s[buf][le0][j] = h[0];
        h_s[buf][le1][j] = h[1];
        __syncwarp();

        // kick next gathers early (t+2 rows; t+3 indices) — overlap with matvec
        const int tn = (t + 3 < T_LEN) ? (t + 3) : (T_LEN - 1);
        const float4 x2_0 = g_tbl[(size_t)i2[0] * HID + j];
        const float4 x2_1 = g_tbl[(size_t)i2[1] * HID + j];
        const int    i3_0 = xcol0[tn];
        const int    i3_1 = xcol1[tn];

        // two independent chains — compiler interleaves
        #pragma unroll
        for (int e = 0; e < 2; ++e) {
            const ulonglong2* hp = (const ulonglong2*)h_s[buf][e ? le1 : le0];
            u64 a0 = 0ull, a1 = 0ull, a2 = 0ull, a3 = 0ull;
            #pragma unroll
            for (int i = 0; i < 4; ++i) {
                const ulonglong2 hv = hp[i];
                a0 = fma2(hv.x, wk[0][2 * i], a0); a0 = fma2(hv.y, wk[0][2 * i + 1], a0);
                a1 = fma2(hv.x, wk[1][2 * i], a1); a1 = fma2(hv.y, wk[1][2 * i + 1], a1);
                a2 = fma2(hv.x, wk[2][2 * i], a2); a2 = fma2(hv.y, wk[2][2 * i + 1], a2);
                a3 = fma2(hv.x, wk[3][2 * i], a3); a3 = fma2(hv.y, wk[3][2 * i + 1], a3);
            }
            const float si = hadd2(a0) + xc[e].x;   // pre-scaled by 0.5
            const float sf = hadd2(a1) + xc[e].y;
            const float sg = hadd2(a2) + xc[e].z;   // unscaled (tanh gate)
            const float so = hadd2(a3) + xc[e].w;

            const float ig = fmaf(tanh_ap(si), 0.5f, 0.5f);
            const float fg = fmaf(tanh_ap(sf), 0.5f, 0.5f);
            const float gg = tanh_ap(sg);
            const float og = fmaf(tanh_ap(so), 0.5f, 0.5f);
            c[e] = fg * c[e] + ig * gg;
            h[e] = og * tanh_ap(c[e]);
        }

        xc[0] = xn[0]; xn[0] = x2_0; i2[0] = i3_0;
        xc[1] = xn[1]; xn[1] = x2_1; i2[1] = i3_1;
    }

    // FC head: reduce over j within this 16-lane group (xor 8..1 stays in-group)
    const float fcw = fc_w[j];
    const float fcb = fc_b[0];
    {
        float v = h[0] * fcw;
        v += __shfl_xor_sync(0xffffffffu, v, 8);
        v += __shfl_xor_sync(0xffffffffu, v, 4);
        v += __shfl_xor_sync(0xffffffffu, v, 2);
        v += __shfl_xor_sync(0xffffffffu, v, 1);
        if (j == 0 && b0 < BATCH)
            out[b0] = fmaf(tanh_ap(0.5f * (v + fcb)), 0.5f, 0.5f);
    }
    {
        float v = h[1] * fcw;
        v += __shfl_xor_sync(0xffffffffu, v, 8);
        v += __shfl_xor_sync(0xffffffffu, v, 4);
        v += __shfl_xor_sync(0xffffffffu, v, 2);
        v += __shfl_xor_sync(0xffffffffu, v, 1);
        if (j == 0 && v1 && b1 < BATCH)
            out[b1] = fmaf(tanh_ap(0.5f * (v + fcb)), 0.5f, 0.5f);
    }
}

extern "C" void kernel_launch(void* const* d_in, const int* in_sizes, int n_in,
                              void* d_out, int out_size)
{
    const int*   x     = (const int*)  d_in[0];
    const float* embed = (const float*)d_in[1];
    const float* w_ih  = (const float*)d_in[2];
    const float* w_hh  = (const float*)d_in[3];
    const float* b_ih  = (const float*)d_in[4];
    const float* b_hh  = (const float*)d_in[5];
    const float* fc_w  = (const float*)d_in[6];
    const float* fc_b  = (const float*)d_in[7];
    float* out = (float*)d_out;

    proj_table_kernel<<<PT_GRID, PT_THREADS>>>(embed, w_ih, b_ih, b_hh);
    recur_kernel<<<RC_GRID, RC_THREADS>>>(x, w_hh, fc_w, fc_b, out);
}